// round 7
// baseline (speedup 1.0000x reference)
#include <cuda_runtime.h>
#include <math.h>

constexpr int B = 16, C = 80, H = 64, W = 64, K = 20;
constexpr int HW = H * W;          // 4096
constexpr int NPAIR = B * K;       // 320
constexpr float PEAK_TEMP = 10.0f;

__device__ float g_partial[NPAIR];

// One block per (b,k) pair. 256 threads, float4 loads (4 iters of 1024 px).
__global__ __launch_bounds__(256) void pair_kernel(
    const float* __restrict__ cam,         // [B,C,H,W]
    const float* __restrict__ pred_boxes,  // [B,C,H,W,4]
    const float* __restrict__ gt_boxes,    // [B,K,4]
    const int*   __restrict__ gt_labels,   // [B,K]
    const float* __restrict__ threshold)   // [1]
{
    const int pair = blockIdx.x;
    const int b    = pair / K;
    const int lab  = gt_labels[pair];

    const float4 g = reinterpret_cast<const float4*>(gt_boxes)[pair];
    const float gx1 = g.x, gy1 = g.y, gx2 = g.z, gy2 = g.w;

    // Rectangular mask bounds (floor + clamp, exactly as _box_masks)
    const int i_min = max(0,     (int)floorf(gy1 * (float)H));
    const int i_max = min(H - 1, (int)floorf(gy2 * (float)H));
    const int j_min = max(0,     (int)floorf(gx1 * (float)W));
    const int j_max = min(W - 1, (int)floorf(gx2 * (float)W));

    const float thr = threshold[0];
    const float* __restrict__ map = cam + ((size_t)(b * C + lab)) * HW;

    const int t = threadIdx.x;

    float s_tot = 0.f, s_in = 0.f;   // cam sums
    float p_tot = 0.f, p_in = 0.f;   // peak (sigmoid) sums
    float best = -INFINITY;
    int bestIdx = HW;

    #pragma unroll
    for (int it = 0; it < HW / (256 * 4); ++it) {   // 4 iterations
        const int q = t + it * 256;
        const float4 v4 = reinterpret_cast<const float4*>(map)[q];
        const int base = q * 4;
        const int i  = base >> 6;     // row (W = 64)
        const int j0 = base & 63;     // first col of quad
        const bool row_in = (i >= i_min) & (i <= i_max);
        const float vv[4] = {v4.x, v4.y, v4.z, v4.w};
        #pragma unroll
        for (int e = 0; e < 4; ++e) {
            const float val = vv[e];
            const float pk = 1.0f / (1.0f + expf((thr - val) * PEAK_TEMP));
            s_tot += val;
            p_tot += pk;
            const int j = j0 + e;
            if (row_in & (j >= j_min) & (j <= j_max)) {
                s_in += val;
                p_in += pk;
                // ascending per-thread order -> strict > keeps first occurrence
                if (val > best) { best = val; bestIdx = base + e; }
            }
        }
    }

    // ---- block reductions (256 = 2^8: full power-of-two trees) ----
    __shared__ float red[256];
    auto block_sum = [&](float v) -> float {
        red[t] = v; __syncthreads();
        #pragma unroll
        for (int s = 128; s > 0; s >>= 1) {
            if (t < s) red[t] += red[t + s];
            __syncthreads();
        }
        const float r = red[0]; __syncthreads();
        return r;
    };
    const float S_tot = block_sum(s_tot);
    const float S_in  = block_sum(s_in);
    const float P_tot = block_sum(p_tot);
    const float P_in  = block_sum(p_in);

    __shared__ float rv[256];
    __shared__ int   ri[256];
    rv[t] = best; ri[t] = bestIdx; __syncthreads();
    #pragma unroll
    for (int s = 128; s > 0; s >>= 1) {
        if (t < s) {
            const float ov = rv[t + s]; const int oi = ri[t + s];
            if (ov > rv[t] || (ov == rv[t] && oi < ri[t])) { rv[t] = ov; ri[t] = oi; }
        }
        __syncthreads();
    }

    if (t == 0) {
        const int   cnt   = (i_max - i_min + 1) * (j_max - j_min + 1);
        const float cnt_f = (float)cnt;
        const float out_f = (float)(HW - cnt);

        const float v_in  = S_in / fmaxf(cnt_f, 1.0f);
        const float v_out = (S_tot - S_in) / fmaxf(out_f, 1.0f);
        const float term_cam = (cnt > 0 ? 1.0f - v_in : 0.0f) +
                               (cnt < HW ? v_out : 0.0f);

        const float pv_in  = P_in / fmaxf(cnt_f, 1.0f);
        const float pv_out = (P_tot - P_in) / fmaxf(out_f, 1.0f);
        const float term_peak = (cnt > 0 ? 1.0f - pv_in : 0.0f) +
                                (cnt < HW ? pv_out : 0.0f);

        // Gather predicted box at argmax location
        const int bi = ri[0];
        const float* pb = pred_boxes + (((size_t)(b * C + lab)) * HW + bi) * 4;
        const float px1 = pb[0], py1 = pb[1], px2 = pb[2], py2 = pb[3];

        // L1 (summed over 4 coords; /4 folded into weight)
        const float l1 = fabsf(px1 - gx1) + fabsf(py1 - gy1) +
                         fabsf(px2 - gx2) + fabsf(py2 - gy2);

        // GIoU
        const float ltx = fmaxf(px1, gx1), lty = fmaxf(py1, gy1);
        const float rbx = fminf(px2, gx2), rby = fminf(py2, gy2);
        const float iw  = fmaxf(rbx - ltx, 0.0f), ih = fmaxf(rby - lty, 0.0f);
        const float inter = iw * ih;
        const float ap = (px2 - px1) * (py2 - py1);
        const float ag = (gx2 - gx1) * (gy2 - gy1);
        const float uni = ap + ag - inter;
        const float iou = inter / uni;
        const float cx1 = fminf(px1, gx1), cy1 = fminf(py1, gy1);
        const float cx2 = fmaxf(px2, gx2), cy2 = fmaxf(py2, gy2);
        const float cw = fmaxf(cx2 - cx1, 0.0f), ch = fmaxf(cy2 - cy1, 0.0f);
        const float ac = cw * ch;
        const float giou = iou - (ac - uni) / ac;

        // Per-pair contribution (all .mean() + lambdas folded in)
        const float inv = 1.0f / (float)NPAIR;
        g_partial[pair] = (l1 * 0.25f +
                           2.0f * (1.0f - giou) +
                           0.5f * term_cam +
                           0.5f * term_peak) * inv;
    }
}

// Final sum of 320 partials. 512 threads = 2^9 -> CORRECT power-of-two tree.
// (The previous 384-thread tree silently dropped red[2]'s lane: the R2-R4 bug.)
__global__ __launch_bounds__(512) void reduce_kernel(float* __restrict__ out, int out_size)
{
    __shared__ float red[512];
    const int t = threadIdx.x;
    red[t] = (t < NPAIR) ? g_partial[t] : 0.0f;
    __syncthreads();
    #pragma unroll
    for (int s = 256; s > 0; s >>= 1) {
        if (t < s) red[t] += red[t + s];
        __syncthreads();
    }
    for (int i = t; i < out_size; i += 512) out[i] = red[0];
}

extern "C" void kernel_launch(void* const* d_in, const int* in_sizes, int n_in,
                              void* d_out, int out_size)
{
    // Bind by element count (all five distinct; validated: identical results
    // to positional binding in R2/R3)
    const float* cam        = nullptr;
    const float* pred_boxes = nullptr;
    const float* gt_boxes   = nullptr;
    const int*   gt_labels  = nullptr;
    const float* threshold  = nullptr;

    for (int i = 0; i < n_in; ++i) {
        switch (in_sizes[i]) {
            case B * C * H * W:       cam        = (const float*)d_in[i]; break;
            case B * C * H * W * 4:   pred_boxes = (const float*)d_in[i]; break;
            case B * K * 4:           gt_boxes   = (const float*)d_in[i]; break;
            case B * K:               gt_labels  = (const int*)d_in[i];   break;
            case 1:                   threshold  = (const float*)d_in[i]; break;
            default: break;
        }
    }

    pair_kernel<<<NPAIR, 256>>>(cam, pred_boxes, gt_boxes, gt_labels, threshold);
    reduce_kernel<<<1, 512>>>((float*)d_out, out_size);
}